// round 2
// baseline (speedup 1.0000x reference)
#include <cuda_runtime.h>
#include <cstdint>

// Problem constants (fixed shapes for this problem)
#define N_NODES 50000
#define D_IN    128
#define D_FF    256
#define D_OUT   119

// Scratch (allocation-free rule: __device__ globals). 16B-aligned for float4 /
// red.global.add.v4.f32 accesses.
__device__ __align__(16) float g_h[(size_t)N_NODES * D_IN];      // 25.6 MB
__device__ __align__(16) float g_aggr[(size_t)N_NODES * D_IN];   // 25.6 MB
__device__ __align__(16) float g_hid[(size_t)N_NODES * D_FF];    // 51.2 MB

// ---------------------------------------------------------------------------
// Tiled fp32 GEMM: C[M,P] = act( op(A)[M,K] @ B[P,K]^T + bias )
//   op(A) = PReLU(A) if PRELU_A
//   act   = relu if RELU_OUT
// BM=64, BP=64, BK=32, 256 threads, 4x4 register tile per thread.
// ---------------------------------------------------------------------------
template<bool PRELU_A, bool RELU_OUT, bool HAS_BIAS>
__global__ __launch_bounds__(256)
void gemm_kernel(const float* __restrict__ A, const float* __restrict__ B,
                 const float* __restrict__ bias, float* __restrict__ C,
                 int M, int K, int P, const float* __restrict__ prelu_a)
{
    const int BM = 64, BP = 64, BK = 32;
    __shared__ float As[BK][BM + 4];   // row stride 68 floats = 272B (16B mult)
    __shared__ float Bs[BK][BP + 4];

    const int tid = threadIdx.x;
    const int tx = tid & 15;        // 0..15 -> P cols
    const int ty = tid >> 4;        // 0..15 -> M rows
    const int m0 = blockIdx.y * BM;
    const int p0 = blockIdx.x * BP;

    float alpha = 0.0f;
    if (PRELU_A) alpha = __ldg(prelu_a);

    float acc[4][4];
#pragma unroll
    for (int i = 0; i < 4; ++i)
#pragma unroll
        for (int j = 0; j < 4; ++j) acc[i][j] = 0.0f;

    for (int k0 = 0; k0 < K; k0 += BK) {
        // Load A tile: 64 rows x 32 cols = 512 float4, 2 per thread
#pragma unroll
        for (int i = 0; i < 2; ++i) {
            int idx = tid + i * 256;
            int row = idx >> 3;           // 8 float4 per row
            int c4  = idx & 7;
            int gr  = m0 + row;
            float4 v = make_float4(0.f, 0.f, 0.f, 0.f);
            if (gr < M)
                v = __ldg((const float4*)(A + (size_t)gr * K + k0 + c4 * 4));
            if (PRELU_A) {
                v.x = v.x > 0.f ? v.x : alpha * v.x;
                v.y = v.y > 0.f ? v.y : alpha * v.y;
                v.z = v.z > 0.f ? v.z : alpha * v.z;
                v.w = v.w > 0.f ? v.w : alpha * v.w;
            }
            As[c4 * 4 + 0][row] = v.x;
            As[c4 * 4 + 1][row] = v.y;
            As[c4 * 4 + 2][row] = v.z;
            As[c4 * 4 + 3][row] = v.w;
        }
        // Load B tile: 64 rows (P) x 32 cols (K)
#pragma unroll
        for (int i = 0; i < 2; ++i) {
            int idx = tid + i * 256;
            int row = idx >> 3;
            int c4  = idx & 7;
            int gp  = p0 + row;
            float4 v = make_float4(0.f, 0.f, 0.f, 0.f);
            if (gp < P)
                v = __ldg((const float4*)(B + (size_t)gp * K + k0 + c4 * 4));
            Bs[c4 * 4 + 0][row] = v.x;
            Bs[c4 * 4 + 1][row] = v.y;
            Bs[c4 * 4 + 2][row] = v.z;
            Bs[c4 * 4 + 3][row] = v.w;
        }
        __syncthreads();

#pragma unroll
        for (int kk = 0; kk < BK; ++kk) {
            float4 av = *(const float4*)&As[kk][ty * 4];
            float4 bv = *(const float4*)&Bs[kk][tx * 4];
            acc[0][0] += av.x * bv.x; acc[0][1] += av.x * bv.y;
            acc[0][2] += av.x * bv.z; acc[0][3] += av.x * bv.w;
            acc[1][0] += av.y * bv.x; acc[1][1] += av.y * bv.y;
            acc[1][2] += av.y * bv.z; acc[1][3] += av.y * bv.w;
            acc[2][0] += av.z * bv.x; acc[2][1] += av.z * bv.y;
            acc[2][2] += av.z * bv.z; acc[2][3] += av.z * bv.w;
            acc[3][0] += av.w * bv.x; acc[3][1] += av.w * bv.y;
            acc[3][2] += av.w * bv.z; acc[3][3] += av.w * bv.w;
        }
        __syncthreads();
    }

#pragma unroll
    for (int i = 0; i < 4; ++i) {
        int gr = m0 + ty * 4 + i;
        if (gr >= M) continue;
#pragma unroll
        for (int j = 0; j < 4; ++j) {
            int gp = p0 + tx * 4 + j;
            if (gp < P) {
                float v = acc[i][j];
                if (HAS_BIAS) v += __ldg(bias + gp);
                if (RELU_OUT) v = fmaxf(v, 0.f);
                C[(size_t)gr * P + gp] = v;
            }
        }
    }
}

// ---------------------------------------------------------------------------
// Zero masked rows of g_h. One warp per masked index. (indices are INT32 —
// JAX default config downcasts jnp.int64 to int32)
// ---------------------------------------------------------------------------
__global__ void mask_kernel(const int* __restrict__ mi, int NM)
{
    int w = (blockIdx.x * blockDim.x + threadIdx.x) >> 5;
    if (w >= NM) return;
    int lane = threadIdx.x & 31;
    int r = __ldg(mi + w);
    if (r < 0 || r >= N_NODES) return;
    *(float4*)(g_h + (size_t)r * D_IN + lane * 4) = make_float4(0.f, 0.f, 0.f, 0.f);
}

// ---------------------------------------------------------------------------
// Self-loop init: aggr[i] = h[i] + emb1[4] + emb2[0]. One thread per float4.
// ---------------------------------------------------------------------------
__global__ void selfloop_kernel(const float* __restrict__ emb1,
                                const float* __restrict__ emb2, int N)
{
    int t = blockIdx.x * blockDim.x + threadIdx.x;
    if (t >= N * (D_IN / 4)) return;
    int i  = t >> 5;               // node
    int c  = (t & 31) * 4;         // column
    float4 hv = *(const float4*)(g_h + (size_t)i * D_IN + c);
    float4 e1 = __ldg((const float4*)(emb1 + 4 * D_IN + c));
    float4 e2 = __ldg((const float4*)(emb2 + 0 * D_IN + c));
    float4 o;
    o.x = hv.x + e1.x + e2.x;
    o.y = hv.y + e1.y + e2.y;
    o.z = hv.z + e1.z + e2.z;
    o.w = hv.w + e1.w + e2.w;
    *(float4*)(g_aggr + (size_t)i * D_IN + c) = o;
}

// ---------------------------------------------------------------------------
// Edge scatter: aggr[dst] += h[src] + emb1[et] + emb2[ed].
// One warp per edge, lane -> float4 chunk, vector red.global.add.v4.f32.
// ---------------------------------------------------------------------------
__global__ void edge_kernel(const int* __restrict__ ei,
                            const int* __restrict__ ea,
                            const float* __restrict__ emb1,
                            const float* __restrict__ emb2, int E)
{
    int w = (blockIdx.x * blockDim.x + threadIdx.x) >> 5;
    if (w >= E) return;
    int lane = threadIdx.x & 31;
    int src = __ldg(ei + w);
    int dst = __ldg(ei + E + w);
    int et  = __ldg(ea + 2 * w);
    int ed  = __ldg(ea + 2 * w + 1);
    int c = lane * 4;
    float4 hv = *(const float4*)(g_h + (size_t)src * D_IN + c);
    float4 e1 = __ldg((const float4*)(emb1 + (size_t)et * D_IN + c));
    float4 e2 = __ldg((const float4*)(emb2 + (size_t)ed * D_IN + c));
    float m0 = hv.x + e1.x + e2.x;
    float m1 = hv.y + e1.y + e2.y;
    float m2 = hv.z + e1.z + e2.z;
    float m3 = hv.w + e1.w + e2.w;
    float* p = g_aggr + (size_t)dst * D_IN + c;
    asm volatile("red.global.add.v4.f32 [%0], {%1, %2, %3, %4};"
                 :: "l"(p), "f"(m0), "f"(m1), "f"(m2), "f"(m3)
                 : "memory");
}

// ---------------------------------------------------------------------------
extern "C" void kernel_launch(void* const* d_in, const int* in_sizes, int n_in,
                              void* d_out, int out_size)
{
    const float* x       = (const float*)d_in[0];
    const int*   ei      = (const int*)d_in[1];
    const int*   ea      = (const int*)d_in[2];
    const int*   mi      = (const int*)d_in[3];
    const float* prelu_a = (const float*)d_in[4];
    const float* W_enc   = (const float*)d_in[5];
    const float* emb1    = (const float*)d_in[6];
    const float* emb2    = (const float*)d_in[7];
    const float* W1      = (const float*)d_in[8];
    const float* b1      = (const float*)d_in[9];
    const float* W2      = (const float*)d_in[10];
    const float* b2      = (const float*)d_in[11];
    float*       out     = (float*)d_out;

    const int N  = in_sizes[0] / D_IN;
    const int E  = in_sizes[1] / 2;
    const int NM = in_sizes[3];

    float *h_ptr, *aggr_ptr, *hid_ptr;
    cudaGetSymbolAddress((void**)&h_ptr, g_h);
    cudaGetSymbolAddress((void**)&aggr_ptr, g_aggr);
    cudaGetSymbolAddress((void**)&hid_ptr, g_hid);

    // 1) h = prelu(x) @ W_enc^T
    {
        dim3 grid((D_IN + 63) / 64, (N + 63) / 64);
        gemm_kernel<true, false, false><<<grid, 256>>>(
            x, W_enc, nullptr, h_ptr, N, D_IN, D_IN, prelu_a);
    }
    // 2) zero masked rows
    {
        int threads = NM * 32;
        mask_kernel<<<(threads + 255) / 256, 256>>>(mi, NM);
    }
    // 3) aggr = h + self-loop embedding
    {
        int threads = N * (D_IN / 4);
        selfloop_kernel<<<(threads + 255) / 256, 256>>>(emb1, emb2, N);
    }
    // 4) edge scatter-add
    {
        long long threads = (long long)E * 32;
        edge_kernel<<<(int)((threads + 255) / 256), 256>>>(ei, ea, emb1, emb2, E);
    }
    // 5) hid = relu(aggr @ W1^T + b1)
    {
        dim3 grid((D_FF + 63) / 64, (N + 63) / 64);
        gemm_kernel<false, true, true><<<grid, 256>>>(
            aggr_ptr, W1, b1, hid_ptr, N, D_IN, D_FF, nullptr);
    }
    // 6) out = hid @ W2^T + b2
    {
        dim3 grid((D_OUT + 63) / 64, (N + 63) / 64);
        gemm_kernel<false, false, true><<<grid, 256>>>(
            hid_ptr, W2, b2, out, N, D_FF, D_OUT, nullptr);
    }
}

// round 3
// speedup vs baseline: 1.4514x; 1.4514x over previous
#include <cuda_runtime.h>
#include <cuda_bf16.h>
#include <cstdint>

// Problem constants (fixed shapes for this problem)
#define N_NODES 50000
#define D_IN    128
#define D_FF    256
#define D_OUT   119

// Scratch (allocation-free rule: __device__ globals). 16B-aligned.
__device__ __align__(16) float g_h[(size_t)N_NODES * D_IN];      // 25.6 MB
__device__ __align__(16) float g_aggr[(size_t)N_NODES * D_IN];   // 25.6 MB
__device__ __align__(16) float g_hid[(size_t)N_NODES * D_FF];    // 51.2 MB

// ---------------------------------------------------------------------------
// bf16-split tensor-core GEMM: C[M,P] = act( op(A)[M,K] @ B[P,K]^T + bias )
// A,B are fp32; each is split into hi/lo bf16 during the smem tile load.
// acc += Ah*Bh + Al*Bh + Ah*Bl  (fp32 accumulate; error ~1e-5)
// BM=128, BN=64, BK=32; 256 threads = 8 warps; warp computes 32x32 output.
// ---------------------------------------------------------------------------

__device__ __forceinline__ void mma16816(float* c, const uint32_t* a,
                                         uint32_t b0, uint32_t b1)
{
    asm volatile(
        "mma.sync.aligned.m16n8k16.row.col.f32.bf16.bf16.f32 "
        "{%0,%1,%2,%3}, {%4,%5,%6,%7}, {%8,%9}, {%0,%1,%2,%3};"
        : "+f"(c[0]), "+f"(c[1]), "+f"(c[2]), "+f"(c[3])
        : "r"(a[0]), "r"(a[1]), "r"(a[2]), "r"(a[3]), "r"(b0), "r"(b1));
}

__device__ __forceinline__ void split_bf16(float x, __nv_bfloat16& hi, __nv_bfloat16& lo)
{
    hi = __float2bfloat16_rn(x);
    lo = __float2bfloat16_rn(x - __bfloat162float(hi));
}

template<bool PRELU_A, bool RELU_OUT, bool HAS_BIAS>
__global__ __launch_bounds__(256)
void gemm_mma_kernel(const float* __restrict__ A, const float* __restrict__ B,
                     const float* __restrict__ bias, float* __restrict__ C,
                     int M, int K, int P, const float* __restrict__ prelu_a)
{
    const int BM = 128, BN = 64, BK = 32;
    const int ASP = 20;  // A smem stride in bf16 PAIRS (40 bf16 = 80B: conflict-free)
    const int BSP = 20;

    // hi/lo bf16 tiles, stored as bf16x2 pairs along k
    __shared__ uint32_t Ah[BM * ASP], Al[BM * ASP];
    __shared__ uint32_t Bh[BN * BSP], Bl[BN * BSP];

    const int tid  = threadIdx.x;
    const int lane = tid & 31;
    const int w    = tid >> 5;
    const int wm   = (w & 3) * 32;   // warp m offset within tile
    const int wn   = (w >> 2) * 32;  // warp n offset within tile
    const int g    = lane >> 2;      // groupID
    const int tg   = lane & 3;       // thread in group
    const int m0   = blockIdx.y * BM;
    const int p0   = blockIdx.x * BN;

    float alpha = 0.0f;
    if (PRELU_A) alpha = __ldg(prelu_a);

    float acc[2][4][4];
#pragma unroll
    for (int mt = 0; mt < 2; ++mt)
#pragma unroll
        for (int nt = 0; nt < 4; ++nt)
#pragma unroll
            for (int i = 0; i < 4; ++i) acc[mt][nt][i] = 0.0f;

    for (int k0 = 0; k0 < K; k0 += BK) {
        // ---- Load A tile (128x32 fp32 -> hi/lo bf16). 1024 float4, 4/thread.
#pragma unroll
        for (int i = 0; i < 4; ++i) {
            int f4  = tid + i * 256;
            int row = f4 >> 3;
            int c4  = f4 & 7;        // float4 index within row (k = c4*4)
            int gr  = m0 + row;
            float4 v = make_float4(0.f, 0.f, 0.f, 0.f);
            if (gr < M)
                v = __ldg((const float4*)(A + (size_t)gr * K + k0 + c4 * 4));
            if (PRELU_A) {
                v.x = v.x > 0.f ? v.x : alpha * v.x;
                v.y = v.y > 0.f ? v.y : alpha * v.y;
                v.z = v.z > 0.f ? v.z : alpha * v.z;
                v.w = v.w > 0.f ? v.w : alpha * v.w;
            }
            __nv_bfloat16 hx, lx, hy, ly, hz, lz, hw, lw;
            split_bf16(v.x, hx, lx); split_bf16(v.y, hy, ly);
            split_bf16(v.z, hz, lz); split_bf16(v.w, hw, lw);
            __nv_bfloat162 h01 = __nv_bfloat162(hx, hy), h23 = __nv_bfloat162(hz, hw);
            __nv_bfloat162 l01 = __nv_bfloat162(lx, ly), l23 = __nv_bfloat162(lz, lw);
            int base = row * ASP + c4 * 2;
            Ah[base]     = *(uint32_t*)&h01;
            Ah[base + 1] = *(uint32_t*)&h23;
            Al[base]     = *(uint32_t*)&l01;
            Al[base + 1] = *(uint32_t*)&l23;
        }
        // ---- Load B tile (64x32 fp32 -> hi/lo bf16). 512 float4, 2/thread.
#pragma unroll
        for (int i = 0; i < 2; ++i) {
            int f4  = tid + i * 256;
            int row = f4 >> 3;       // n index
            int c4  = f4 & 7;
            int gp  = p0 + row;
            float4 v = make_float4(0.f, 0.f, 0.f, 0.f);
            if (gp < P)
                v = __ldg((const float4*)(B + (size_t)gp * K + k0 + c4 * 4));
            __nv_bfloat16 hx, lx, hy, ly, hz, lz, hw, lw;
            split_bf16(v.x, hx, lx); split_bf16(v.y, hy, ly);
            split_bf16(v.z, hz, lz); split_bf16(v.w, hw, lw);
            __nv_bfloat162 h01 = __nv_bfloat162(hx, hy), h23 = __nv_bfloat162(hz, hw);
            __nv_bfloat162 l01 = __nv_bfloat162(lx, ly), l23 = __nv_bfloat162(lz, lw);
            int base = row * BSP + c4 * 2;
            Bh[base]     = *(uint32_t*)&h01;
            Bh[base + 1] = *(uint32_t*)&h23;
            Bl[base]     = *(uint32_t*)&l01;
            Bl[base + 1] = *(uint32_t*)&l23;
        }
        __syncthreads();

        // ---- MMA over the BK tile, two k16 steps
#pragma unroll
        for (int ks = 0; ks < 2; ++ks) {
            int kp = ks * 8 + tg;   // pair index of (tg*2) within this k16: ks*16/2 + tg

            uint32_t ah[2][4], al[2][4];
#pragma unroll
            for (int mt = 0; mt < 2; ++mt) {
                int r = wm + mt * 16 + g;
                ah[mt][0] = Ah[r * ASP + kp];
                ah[mt][1] = Ah[(r + 8) * ASP + kp];
                ah[mt][2] = Ah[r * ASP + kp + 4];
                ah[mt][3] = Ah[(r + 8) * ASP + kp + 4];
                al[mt][0] = Al[r * ASP + kp];
                al[mt][1] = Al[(r + 8) * ASP + kp];
                al[mt][2] = Al[r * ASP + kp + 4];
                al[mt][3] = Al[(r + 8) * ASP + kp + 4];
            }
#pragma unroll
            for (int nt = 0; nt < 4; ++nt) {
                int n = wn + nt * 8 + g;
                uint32_t bh0 = Bh[n * BSP + kp];
                uint32_t bh1 = Bh[n * BSP + kp + 4];
                uint32_t bl0 = Bl[n * BSP + kp];
                uint32_t bl1 = Bl[n * BSP + kp + 4];
#pragma unroll
                for (int mt = 0; mt < 2; ++mt) {
                    mma16816(acc[mt][nt], ah[mt], bh0, bh1);
                    mma16816(acc[mt][nt], al[mt], bh0, bh1);
                    mma16816(acc[mt][nt], ah[mt], bl0, bl1);
                }
            }
        }
        __syncthreads();
    }

    // ---- Epilogue
#pragma unroll
    for (int mt = 0; mt < 2; ++mt) {
#pragma unroll
        for (int nt = 0; nt < 4; ++nt) {
            int row0 = m0 + wm + mt * 16 + g;
            int col  = p0 + wn + nt * 8 + tg * 2;
            float b0 = 0.f, b1 = 0.f;
            if (HAS_BIAS) {
                if (col < P)     b0 = __ldg(bias + col);
                if (col + 1 < P) b1 = __ldg(bias + col + 1);
            }
#pragma unroll
            for (int h = 0; h < 2; ++h) {
                int row = row0 + h * 8;
                if (row >= M) continue;
                float v0 = acc[mt][nt][h * 2 + 0] + b0;
                float v1 = acc[mt][nt][h * 2 + 1] + b1;
                if (RELU_OUT) { v0 = fmaxf(v0, 0.f); v1 = fmaxf(v1, 0.f); }
                if (col < P)     C[(size_t)row * P + col]     = v0;
                if (col + 1 < P) C[(size_t)row * P + col + 1] = v1;
            }
        }
    }
}

// ---------------------------------------------------------------------------
// Zero masked rows of g_h. One warp per masked index (int32 indices).
// ---------------------------------------------------------------------------
__global__ void mask_kernel(const int* __restrict__ mi, int NM)
{
    int w = (blockIdx.x * blockDim.x + threadIdx.x) >> 5;
    if (w >= NM) return;
    int lane = threadIdx.x & 31;
    int r = __ldg(mi + w);
    if (r < 0 || r >= N_NODES) return;
    *(float4*)(g_h + (size_t)r * D_IN + lane * 4) = make_float4(0.f, 0.f, 0.f, 0.f);
}

// ---------------------------------------------------------------------------
// Self-loop init: aggr[i] = h[i] + emb1[4] + emb2[0].
// ---------------------------------------------------------------------------
__global__ void selfloop_kernel(const float* __restrict__ emb1,
                                const float* __restrict__ emb2, int N)
{
    int t = blockIdx.x * blockDim.x + threadIdx.x;
    if (t >= N * (D_IN / 4)) return;
    int i  = t >> 5;
    int c  = (t & 31) * 4;
    float4 hv = *(const float4*)(g_h + (size_t)i * D_IN + c);
    float4 e1 = __ldg((const float4*)(emb1 + 4 * D_IN + c));
    float4 e2 = __ldg((const float4*)(emb2 + 0 * D_IN + c));
    float4 o;
    o.x = hv.x + e1.x + e2.x;
    o.y = hv.y + e1.y + e2.y;
    o.z = hv.z + e1.z + e2.z;
    o.w = hv.w + e1.w + e2.w;
    *(float4*)(g_aggr + (size_t)i * D_IN + c) = o;
}

// ---------------------------------------------------------------------------
// Edge scatter: aggr[dst] += h[src] + emb1[et] + emb2[ed].
// One warp per TWO edges (independent chains -> 2x MLP), vector red.add.
// ---------------------------------------------------------------------------
__global__ void edge_kernel(const int* __restrict__ ei,
                            const int* __restrict__ ea,
                            const float* __restrict__ emb1,
                            const float* __restrict__ emb2, int E)
{
    int w = (blockIdx.x * blockDim.x + threadIdx.x) >> 5;
    int lane = threadIdx.x & 31;
    int c = lane * 4;
#pragma unroll
    for (int j = 0; j < 2; ++j) {
        int e = w * 2 + j;
        if (e >= E) return;
        int src = __ldg(ei + e);
        int dst = __ldg(ei + E + e);
        int et  = __ldg(ea + 2 * e);
        int ed  = __ldg(ea + 2 * e + 1);
        float4 hv = *(const float4*)(g_h + (size_t)src * D_IN + c);
        float4 e1 = __ldg((const float4*)(emb1 + (size_t)et * D_IN + c));
        float4 e2 = __ldg((const float4*)(emb2 + (size_t)ed * D_IN + c));
        float m0 = hv.x + e1.x + e2.x;
        float m1 = hv.y + e1.y + e2.y;
        float m2 = hv.z + e1.z + e2.z;
        float m3 = hv.w + e1.w + e2.w;
        float* p = g_aggr + (size_t)dst * D_IN + c;
        asm volatile("red.global.add.v4.f32 [%0], {%1, %2, %3, %4};"
                     :: "l"(p), "f"(m0), "f"(m1), "f"(m2), "f"(m3)
                     : "memory");
    }
}

// ---------------------------------------------------------------------------
extern "C" void kernel_launch(void* const* d_in, const int* in_sizes, int n_in,
                              void* d_out, int out_size)
{
    const float* x       = (const float*)d_in[0];
    const int*   ei      = (const int*)d_in[1];
    const int*   ea      = (const int*)d_in[2];
    const int*   mi      = (const int*)d_in[3];
    const float* prelu_a = (const float*)d_in[4];
    const float* W_enc   = (const float*)d_in[5];
    const float* emb1    = (const float*)d_in[6];
    const float* emb2    = (const float*)d_in[7];
    const float* W1      = (const float*)d_in[8];
    const float* b1      = (const float*)d_in[9];
    const float* W2      = (const float*)d_in[10];
    const float* b2      = (const float*)d_in[11];
    float*       out     = (float*)d_out;

    const int N  = in_sizes[0] / D_IN;
    const int E  = in_sizes[1] / 2;
    const int NM = in_sizes[3];

    float *h_ptr, *aggr_ptr, *hid_ptr;
    cudaGetSymbolAddress((void**)&h_ptr, g_h);
    cudaGetSymbolAddress((void**)&aggr_ptr, g_aggr);
    cudaGetSymbolAddress((void**)&hid_ptr, g_hid);

    // 1) h = prelu(x) @ W_enc^T
    {
        dim3 grid((D_IN + 63) / 64, (N + 127) / 128);
        gemm_mma_kernel<true, false, false><<<grid, 256>>>(
            x, W_enc, nullptr, h_ptr, N, D_IN, D_IN, prelu_a);
    }
    // 2) zero masked rows
    {
        int threads = NM * 32;
        mask_kernel<<<(threads + 255) / 256, 256>>>(mi, NM);
    }
    // 3) aggr = h + self-loop embedding
    {
        int threads = N * (D_IN / 4);
        selfloop_kernel<<<(threads + 255) / 256, 256>>>(emb1, emb2, N);
    }
    // 4) edge scatter-add (2 edges per warp)
    {
        int warps = (E + 1) / 2;
        long long threads = (long long)warps * 32;
        edge_kernel<<<(int)((threads + 255) / 256), 256>>>(ei, ea, emb1, emb2, E);
    }
    // 5) hid = relu(aggr @ W1^T + b1)
    {
        dim3 grid((D_FF + 63) / 64, (N + 127) / 128);
        gemm_mma_kernel<false, true, true><<<grid, 256>>>(
            aggr_ptr, W1, b1, hid_ptr, N, D_IN, D_FF, nullptr);
    }
    // 6) out = hid @ W2^T + b2
    {
        dim3 grid((D_OUT + 63) / 64, (N + 127) / 128);
        gemm_mma_kernel<false, false, true><<<grid, 256>>>(
            hid_ptr, W2, b2, out, N, D_FF, D_OUT, nullptr);
    }
}

// round 4
// speedup vs baseline: 1.5554x; 1.0716x over previous
#include <cuda_runtime.h>
#include <cuda_bf16.h>
#include <cstdint>

// Problem constants (fixed shapes for this problem)
#define N_NODES 50000
#define D_IN    128
#define D_FF    256
#define D_OUT   119

// Scratch (allocation-free rule: __device__ globals). 16B-aligned.
__device__ __align__(16) float g_h[(size_t)N_NODES * D_IN];      // 25.6 MB
__device__ __align__(16) float g_aggr[(size_t)N_NODES * D_IN];   // 25.6 MB
__device__ __align__(16) float g_hid[(size_t)N_NODES * D_FF];    // 51.2 MB
__device__ unsigned g_maskbits[(N_NODES + 31) / 32];             // 6.25 KB

// ---------------------------------------------------------------------------
// MMA + ldmatrix primitives
// ---------------------------------------------------------------------------
__device__ __forceinline__ void mma16816(float* c, const uint32_t* a,
                                         uint32_t b0, uint32_t b1)
{
    asm volatile(
        "mma.sync.aligned.m16n8k16.row.col.f32.bf16.bf16.f32 "
        "{%0,%1,%2,%3}, {%4,%5,%6,%7}, {%8,%9}, {%0,%1,%2,%3};"
        : "+f"(c[0]), "+f"(c[1]), "+f"(c[2]), "+f"(c[3])
        : "r"(a[0]), "r"(a[1]), "r"(a[2]), "r"(a[3]), "r"(b0), "r"(b1));
}

__device__ __forceinline__ void ldsm4(uint32_t* r, const uint32_t* p)
{
    uint32_t a = (uint32_t)__cvta_generic_to_shared(p);
    asm volatile("ldmatrix.sync.aligned.m8n8.x4.shared.b16 {%0,%1,%2,%3}, [%4];"
                 : "=r"(r[0]), "=r"(r[1]), "=r"(r[2]), "=r"(r[3]) : "r"(a));
}

__device__ __forceinline__ void split_bf16(float x, __nv_bfloat16& hi, __nv_bfloat16& lo)
{
    hi = __float2bfloat16_rn(x);
    lo = __float2bfloat16_rn(x - __bfloat162float(hi));
}

// ---------------------------------------------------------------------------
// bf16-split tensor-core GEMM: C[M,P] = act( op(A)[M,K] @ B[P,K]^T + bias )
// acc += Ah*Bh + Al*Bh + Ah*Bl  (fp32 accumulate; error ~1e-5)
// BM=128, BN=64, BK=32; 256 threads = 8 warps; warp computes 32x32 output.
// FUSED_MASK_SELFLOOP (GEMM1 only): also writes
//   h_row = masked ? 0 : v ;  C=h ;  C2(aggr) = h_row + emb1[4]+emb2[0]
// ---------------------------------------------------------------------------
template<bool PRELU_A, bool RELU_OUT, bool HAS_BIAS, bool FUSED_MS>
__global__ __launch_bounds__(256)
void gemm_mma_kernel(const float* __restrict__ A, const float* __restrict__ B,
                     const float* __restrict__ bias, float* __restrict__ C,
                     float* __restrict__ C2,
                     int M, int K, int P, const float* __restrict__ prelu_a,
                     const float* __restrict__ emb1, const float* __restrict__ emb2)
{
    const int BM = 128, BN = 64;
    const int ASP = 20;  // smem stride in bf16 PAIRS (40 bf16 = 80B: LDSM conflict-free)
    const int BSP = 20;

    __shared__ uint32_t Ah[BM * ASP], Al[BM * ASP];
    __shared__ uint32_t Bh[BN * BSP], Bl[BN * BSP];

    const int tid  = threadIdx.x;
    const int lane = tid & 31;
    const int w    = tid >> 5;
    const int wm   = (w & 3) * 32;   // warp m offset within tile
    const int wn   = (w >> 2) * 32;  // warp n offset within tile
    const int g    = lane >> 2;      // groupID
    const int tg   = lane & 3;       // thread in group
    const int m0   = blockIdx.y * BM;
    const int p0   = blockIdx.x * BN;

    float alpha = 0.0f;
    if (PRELU_A) alpha = __ldg(prelu_a);

    float acc[2][4][4];
#pragma unroll
    for (int mt = 0; mt < 2; ++mt)
#pragma unroll
        for (int nt = 0; nt < 4; ++nt)
#pragma unroll
            for (int i = 0; i < 4; ++i) acc[mt][nt][i] = 0.0f;

    // ldmatrix per-lane source addresses (constant across k-iters except kpair)
    const int a_row = lane & 15;            // + m_base
    const int a_kp0 = (lane >> 4) * 4;      // + ks*8
    const int b_row = ((lane >> 4) & 1) * 8 + (lane & 7);  // + n_base
    const int b_kp0 = ((lane >> 3) & 1) * 4;               // + ks*8

    for (int k0 = 0; k0 < K; k0 += 32) {
        // ---- Load A tile (128x32 fp32 -> hi/lo bf16). 1024 float4, 4/thread.
#pragma unroll
        for (int i = 0; i < 4; ++i) {
            int f4  = tid + i * 256;
            int row = f4 >> 3;
            int c4  = f4 & 7;
            int gr  = m0 + row;
            float4 v = make_float4(0.f, 0.f, 0.f, 0.f);
            if (gr < M)
                v = __ldg((const float4*)(A + (size_t)gr * K + k0 + c4 * 4));
            if (PRELU_A) {
                v.x = v.x > 0.f ? v.x : alpha * v.x;
                v.y = v.y > 0.f ? v.y : alpha * v.y;
                v.z = v.z > 0.f ? v.z : alpha * v.z;
                v.w = v.w > 0.f ? v.w : alpha * v.w;
            }
            __nv_bfloat16 hx, lx, hy, ly, hz, lz, hw, lw;
            split_bf16(v.x, hx, lx); split_bf16(v.y, hy, ly);
            split_bf16(v.z, hz, lz); split_bf16(v.w, hw, lw);
            __nv_bfloat162 h01 = __nv_bfloat162(hx, hy), h23 = __nv_bfloat162(hz, hw);
            __nv_bfloat162 l01 = __nv_bfloat162(lx, ly), l23 = __nv_bfloat162(lz, lw);
            int base = row * ASP + c4 * 2;
            Ah[base]     = *(uint32_t*)&h01;
            Ah[base + 1] = *(uint32_t*)&h23;
            Al[base]     = *(uint32_t*)&l01;
            Al[base + 1] = *(uint32_t*)&l23;
        }
        // ---- Load B tile (64x32 fp32 -> hi/lo bf16). 512 float4, 2/thread.
#pragma unroll
        for (int i = 0; i < 2; ++i) {
            int f4  = tid + i * 256;
            int row = f4 >> 3;
            int c4  = f4 & 7;
            int gp  = p0 + row;
            float4 v = make_float4(0.f, 0.f, 0.f, 0.f);
            if (gp < P)
                v = __ldg((const float4*)(B + (size_t)gp * K + k0 + c4 * 4));
            __nv_bfloat16 hx, lx, hy, ly, hz, lz, hw, lw;
            split_bf16(v.x, hx, lx); split_bf16(v.y, hy, ly);
            split_bf16(v.z, hz, lz); split_bf16(v.w, hw, lw);
            __nv_bfloat162 h01 = __nv_bfloat162(hx, hy), h23 = __nv_bfloat162(hz, hw);
            __nv_bfloat162 l01 = __nv_bfloat162(lx, ly), l23 = __nv_bfloat162(lz, lw);
            int base = row * BSP + c4 * 2;
            Bh[base]     = *(uint32_t*)&h01;
            Bh[base + 1] = *(uint32_t*)&h23;
            Bl[base]     = *(uint32_t*)&l01;
            Bl[base + 1] = *(uint32_t*)&l23;
        }
        __syncthreads();

        // ---- MMA over the BK tile, two k16 steps, ldmatrix fragments
#pragma unroll
        for (int ks = 0; ks < 2; ++ks) {
            uint32_t ah[2][4], al[2][4], bh[2][4], bl[2][4];
            int akp = ks * 8 + a_kp0;
            int bkp = ks * 8 + b_kp0;
#pragma unroll
            for (int mt = 0; mt < 2; ++mt) {
                int r = wm + mt * 16 + a_row;
                ldsm4(ah[mt], &Ah[r * ASP + akp]);
                ldsm4(al[mt], &Al[r * ASP + akp]);
            }
#pragma unroll
            for (int p = 0; p < 2; ++p) {
                int n = wn + p * 16 + b_row;
                ldsm4(bh[p], &Bh[n * BSP + bkp]);
                ldsm4(bl[p], &Bl[n * BSP + bkp]);
            }
#pragma unroll
            for (int p = 0; p < 2; ++p) {
#pragma unroll
                for (int half = 0; half < 2; ++half) {
                    int nt = p * 2 + half;
                    uint32_t b0  = bh[p][half * 2], b1  = bh[p][half * 2 + 1];
                    uint32_t lb0 = bl[p][half * 2], lb1 = bl[p][half * 2 + 1];
#pragma unroll
                    for (int mt = 0; mt < 2; ++mt) {
                        mma16816(acc[mt][nt], ah[mt], b0, b1);
                        mma16816(acc[mt][nt], al[mt], b0, b1);
                        mma16816(acc[mt][nt], ah[mt], lb0, lb1);
                    }
                }
            }
        }
        __syncthreads();
    }

    // ---- Epilogue
#pragma unroll
    for (int mt = 0; mt < 2; ++mt) {
#pragma unroll
        for (int nt = 0; nt < 4; ++nt) {
            int row0 = m0 + wm + mt * 16 + g;
            int col  = p0 + wn + nt * 8 + tg * 2;
            float b0 = 0.f, b1 = 0.f;
            if (HAS_BIAS) {
                if (col < P)     b0 = __ldg(bias + col);
                if (col + 1 < P) b1 = __ldg(bias + col + 1);
            }
            float ec0 = 0.f, ec1 = 0.f;
            if (FUSED_MS) {
                // emb1[4] + emb2[0], per column (P == D_IN here)
                ec0 = __ldg(emb1 + 4 * D_IN + col) + __ldg(emb2 + col);
                ec1 = __ldg(emb1 + 4 * D_IN + col + 1) + __ldg(emb2 + col + 1);
            }
#pragma unroll
            for (int h = 0; h < 2; ++h) {
                int row = row0 + h * 8;
                if (row >= M) continue;
                float v0 = acc[mt][nt][h * 2 + 0] + b0;
                float v1 = acc[mt][nt][h * 2 + 1] + b1;
                if (RELU_OUT) { v0 = fmaxf(v0, 0.f); v1 = fmaxf(v1, 0.f); }
                if (FUSED_MS) {
                    bool masked = (__ldg(&g_maskbits[row >> 5]) >> (row & 31)) & 1u;
                    if (masked) { v0 = 0.f; v1 = 0.f; }
                    C[(size_t)row * P + col]      = v0;
                    C[(size_t)row * P + col + 1]  = v1;
                    C2[(size_t)row * P + col]     = v0 + ec0;
                    C2[(size_t)row * P + col + 1] = v1 + ec1;
                } else {
                    if (col < P)     C[(size_t)row * P + col]     = v0;
                    if (col + 1 < P) C[(size_t)row * P + col + 1] = v1;
                }
            }
        }
    }
}

// ---------------------------------------------------------------------------
// Build mask bitmap. Single block: zero then set.
// ---------------------------------------------------------------------------
__global__ void maskbits_kernel(const int* __restrict__ mi, int NM)
{
    const int W = (N_NODES + 31) / 32;
    for (int i = threadIdx.x; i < W; i += blockDim.x) g_maskbits[i] = 0u;
    __syncthreads();
    for (int i = threadIdx.x; i < NM; i += blockDim.x) {
        int r = __ldg(mi + i);
        if (r >= 0 && r < N_NODES)
            atomicOr(&g_maskbits[r >> 5], 1u << (r & 31));
    }
}

// ---------------------------------------------------------------------------
// Edge scatter: aggr[dst] += h[src] + emb1[et] + emb2[ed].
// One warp per FOUR edges, software-pipelined gathers, vector red.add.
// ---------------------------------------------------------------------------
__global__ void edge_kernel(const int* __restrict__ ei,
                            const int* __restrict__ ea,
                            const float* __restrict__ emb1,
                            const float* __restrict__ emb2, int E)
{
    int w = (blockIdx.x * blockDim.x + threadIdx.x) >> 5;
    int lane = threadIdx.x & 31;
    int c = lane * 4;
    int base = w * 4;
    if (base >= E) return;

    int src[4], dst[4], et[4], ed[4];
#pragma unroll
    for (int j = 0; j < 4; ++j) {
        int e = base + j;
        if (e < E) {
            src[j] = __ldg(ei + e);
            dst[j] = __ldg(ei + E + e);
            et[j]  = __ldg(ea + 2 * e);
            ed[j]  = __ldg(ea + 2 * e + 1);
        } else { src[j] = 0; dst[j] = -1; et[j] = 0; ed[j] = 0; }
    }
    float4 hv[4], e1[4], e2[4];
#pragma unroll
    for (int j = 0; j < 4; ++j) {
        hv[j] = *(const float4*)(g_h + (size_t)src[j] * D_IN + c);
        e1[j] = __ldg((const float4*)(emb1 + (size_t)et[j] * D_IN + c));
        e2[j] = __ldg((const float4*)(emb2 + (size_t)ed[j] * D_IN + c));
    }
#pragma unroll
    for (int j = 0; j < 4; ++j) {
        if (dst[j] < 0) continue;
        float m0 = hv[j].x + e1[j].x + e2[j].x;
        float m1 = hv[j].y + e1[j].y + e2[j].y;
        float m2 = hv[j].z + e1[j].z + e2[j].z;
        float m3 = hv[j].w + e1[j].w + e2[j].w;
        float* p = g_aggr + (size_t)dst[j] * D_IN + c;
        asm volatile("red.global.add.v4.f32 [%0], {%1, %2, %3, %4};"
                     :: "l"(p), "f"(m0), "f"(m1), "f"(m2), "f"(m3)
                     : "memory");
    }
}

// ---------------------------------------------------------------------------
extern "C" void kernel_launch(void* const* d_in, const int* in_sizes, int n_in,
                              void* d_out, int out_size)
{
    const float* x       = (const float*)d_in[0];
    const int*   ei      = (const int*)d_in[1];
    const int*   ea      = (const int*)d_in[2];
    const int*   mi      = (const int*)d_in[3];
    const float* prelu_a = (const float*)d_in[4];
    const float* W_enc   = (const float*)d_in[5];
    const float* emb1    = (const float*)d_in[6];
    const float* emb2    = (const float*)d_in[7];
    const float* W1      = (const float*)d_in[8];
    const float* b1      = (const float*)d_in[9];
    const float* W2      = (const float*)d_in[10];
    const float* b2      = (const float*)d_in[11];
    float*       out     = (float*)d_out;

    const int N  = in_sizes[0] / D_IN;
    const int E  = in_sizes[1] / 2;
    const int NM = in_sizes[3];

    float *h_ptr, *aggr_ptr, *hid_ptr;
    cudaGetSymbolAddress((void**)&h_ptr, g_h);
    cudaGetSymbolAddress((void**)&aggr_ptr, g_aggr);
    cudaGetSymbolAddress((void**)&hid_ptr, g_hid);

    // 0) mask bitmap
    maskbits_kernel<<<1, 1024>>>(mi, NM);

    // 1) h = mask(prelu(x) @ W_enc^T); aggr = h + emb1[4]+emb2[0]   (fused)
    {
        dim3 grid((D_IN + 63) / 64, (N + 127) / 128);
        gemm_mma_kernel<true, false, false, true><<<grid, 256>>>(
            x, W_enc, nullptr, h_ptr, aggr_ptr, N, D_IN, D_IN, prelu_a, emb1, emb2);
    }
    // 2) edge scatter-add (4 edges per warp)
    {
        int warps = (E + 3) / 4;
        long long threads = (long long)warps * 32;
        edge_kernel<<<(int)((threads + 255) / 256), 256>>>(ei, ea, emb1, emb2, E);
    }
    // 3) hid = relu(aggr @ W1^T + b1)
    {
        dim3 grid((D_FF + 63) / 64, (N + 127) / 128);
        gemm_mma_kernel<false, true, true, false><<<grid, 256>>>(
            aggr_ptr, W1, b1, hid_ptr, nullptr, N, D_IN, D_FF, nullptr, nullptr, nullptr);
    }
    // 4) out = hid @ W2^T + b2
    {
        dim3 grid((D_OUT + 63) / 64, (N + 127) / 128);
        gemm_mma_kernel<false, false, true, false><<<grid, 256>>>(
            hid_ptr, W2, b2, out, nullptr, N, D_FF, D_OUT, nullptr, nullptr, nullptr);
    }
}

// round 6
// speedup vs baseline: 1.6788x; 1.0793x over previous
#include <cuda_runtime.h>
#include <cuda_bf16.h>
#include <cstdint>

// Problem constants (fixed shapes for this problem)
#define N_NODES 50000
#define D_IN    128
#define D_FF    256
#define D_OUT   119

// Scratch (allocation-free rule: __device__ globals). 16B-aligned.
__device__ __align__(16) float g_h[(size_t)N_NODES * D_IN];      // 25.6 MB
__device__ __align__(16) float g_aggr[(size_t)N_NODES * D_IN];   // 25.6 MB
__device__ __align__(16) float g_hid[(size_t)N_NODES * D_FF];    // 51.2 MB
__device__ unsigned g_maskbits[(N_NODES + 31) / 32];             // 6.25 KB

// ---------------------------------------------------------------------------
// MMA + ldmatrix primitives
// ---------------------------------------------------------------------------
__device__ __forceinline__ void mma16816(float* c, const uint32_t* a,
                                         uint32_t b0, uint32_t b1)
{
    asm volatile(
        "mma.sync.aligned.m16n8k16.row.col.f32.bf16.bf16.f32 "
        "{%0,%1,%2,%3}, {%4,%5,%6,%7}, {%8,%9}, {%0,%1,%2,%3};"
        : "+f"(c[0]), "+f"(c[1]), "+f"(c[2]), "+f"(c[3])
        : "r"(a[0]), "r"(a[1]), "r"(a[2]), "r"(a[3]), "r"(b0), "r"(b1));
}

__device__ __forceinline__ void ldsm4(uint32_t* r, const uint32_t* p)
{
    uint32_t a = (uint32_t)__cvta_generic_to_shared(p);
    asm volatile("ldmatrix.sync.aligned.m8n8.x4.shared.b16 {%0,%1,%2,%3}, [%4];"
                 : "=r"(r[0]), "=r"(r[1]), "=r"(r[2]), "=r"(r[3]) : "r"(a));
}

__device__ __forceinline__ void split_bf16(float x, __nv_bfloat16& hi, __nv_bfloat16& lo)
{
    hi = __float2bfloat16_rn(x);
    lo = __float2bfloat16_rn(x - __bfloat162float(hi));
}

// Convert a float4 into hi/lo bf16x2 pair words
__device__ __forceinline__ void cvt4(const float4& v, uint32_t& h0, uint32_t& h1,
                                     uint32_t& l0, uint32_t& l1)
{
    __nv_bfloat16 hx, lx, hy, ly, hz, lz, hw, lw;
    split_bf16(v.x, hx, lx); split_bf16(v.y, hy, ly);
    split_bf16(v.z, hz, lz); split_bf16(v.w, hw, lw);
    __nv_bfloat162 a = __nv_bfloat162(hx, hy), b = __nv_bfloat162(hz, hw);
    __nv_bfloat162 c = __nv_bfloat162(lx, ly), d = __nv_bfloat162(lz, lw);
    h0 = *(uint32_t*)&a; h1 = *(uint32_t*)&b;
    l0 = *(uint32_t*)&c; l1 = *(uint32_t*)&d;
}

// ---------------------------------------------------------------------------
// bf16-split tensor-core GEMM, 2-stage software pipeline.
// C[M,P] = act( op(A)[M,K] @ B[P,K]^T + bias )
// acc += Ah*Bh + Al*Bh + Ah*Bl  (fp32 accumulate; error ~1e-5)
// BM=128, BN=64, BK=32; 256 threads = 8 warps; warp computes 32x32 output.
// ---------------------------------------------------------------------------
#define BMg 128
#define BNg 64
#define ASP 20   /* A smem stride in bf16 PAIRS (40 bf16 = 80B) */
#define BSP 20
#define SMEM_WORDS (4 * BMg * ASP + 4 * BNg * BSP)   /* 15360 words = 61440 B */

template<bool PRELU_A, bool RELU_OUT, bool HAS_BIAS, bool FUSED_MS>
__global__ __launch_bounds__(256, 2)
void gemm_mma_kernel(const float* __restrict__ A, const float* __restrict__ B,
                     const float* __restrict__ bias, float* __restrict__ C,
                     float* __restrict__ C2,
                     int M, int K, int P, const float* __restrict__ prelu_a,
                     const float* __restrict__ emb1, const float* __restrict__ emb2)
{
    extern __shared__ uint32_t smem[];
    uint32_t* AH = smem;                             // [2][BMg*ASP]
    uint32_t* AL = smem + 2 * BMg * ASP;             // [2][BMg*ASP]
    uint32_t* BH = smem + 4 * BMg * ASP;             // [2][BNg*BSP]
    uint32_t* BL = smem + 4 * BMg * ASP + 2 * BNg * BSP;

    const int tid  = threadIdx.x;
    const int lane = tid & 31;
    const int w    = tid >> 5;
    const int wm   = (w & 3) * 32;
    const int wn   = (w >> 2) * 32;
    const int g    = lane >> 2;
    const int tg   = lane & 3;
    const int m0   = blockIdx.y * BMg;
    const int p0   = blockIdx.x * BNg;

    float alpha = 0.0f;
    if (PRELU_A) alpha = __ldg(prelu_a);

    // Per-thread tile-load coordinates (fixed across iterations)
    int arow[4], ac4[4]; bool apred[4];
#pragma unroll
    for (int i = 0; i < 4; ++i) {
        int f4 = tid + i * 256;
        arow[i] = f4 >> 3; ac4[i] = f4 & 7;
        apred[i] = (m0 + arow[i]) < M;
    }
    int brow[2], bc4[2]; bool bpred[2];
#pragma unroll
    for (int i = 0; i < 2; ++i) {
        int f4 = tid + i * 256;
        brow[i] = f4 >> 3; bc4[i] = f4 & 7;
        bpred[i] = (p0 + brow[i]) < P;
    }

    // ldmatrix per-lane addressing
    const int a_row = lane & 15;
    const int a_kp0 = (lane >> 4) * 4;
    const int b_row = ((lane >> 4) & 1) * 8 + (lane & 7);
    const int b_kp0 = ((lane >> 3) & 1) * 4;

    float acc[2][4][4];
#pragma unroll
    for (int mt = 0; mt < 2; ++mt)
#pragma unroll
        for (int nt = 0; nt < 4; ++nt)
#pragma unroll
            for (int i = 0; i < 4; ++i) acc[mt][nt][i] = 0.0f;

    float4 pa[4], pb[2];

    // ---- prologue: load k0=0 tile into regs, store to stage 0
#pragma unroll
    for (int i = 0; i < 4; ++i)
        pa[i] = apred[i] ? __ldg((const float4*)(A + (size_t)(m0 + arow[i]) * K + ac4[i] * 4))
                         : make_float4(0.f, 0.f, 0.f, 0.f);
#pragma unroll
    for (int i = 0; i < 2; ++i)
        pb[i] = bpred[i] ? __ldg((const float4*)(B + (size_t)(p0 + brow[i]) * K + bc4[i] * 4))
                         : make_float4(0.f, 0.f, 0.f, 0.f);
    {
#pragma unroll
        for (int i = 0; i < 4; ++i) {
            float4 v = pa[i];
            if (PRELU_A) {
                v.x = v.x > 0.f ? v.x : alpha * v.x;
                v.y = v.y > 0.f ? v.y : alpha * v.y;
                v.z = v.z > 0.f ? v.z : alpha * v.z;
                v.w = v.w > 0.f ? v.w : alpha * v.w;
            }
            uint32_t h0, h1, l0, l1; cvt4(v, h0, h1, l0, l1);
            int base = arow[i] * ASP + ac4[i] * 2;
            AH[base] = h0; AH[base + 1] = h1;
            AL[base] = l0; AL[base + 1] = l1;
        }
#pragma unroll
        for (int i = 0; i < 2; ++i) {
            uint32_t h0, h1, l0, l1; cvt4(pb[i], h0, h1, l0, l1);
            int base = brow[i] * BSP + bc4[i] * 2;
            BH[base] = h0; BH[base + 1] = h1;
            BL[base] = l0; BL[base + 1] = l1;
        }
    }
    __syncthreads();

    const int niter = K / 32;
    for (int it = 0; it < niter; ++it) {
        const int cur = it & 1;
        const bool has_next = (it + 1) < niter;
        const int knext = (it + 1) * 32;

        // ---- issue next tile's LDGs early
        if (has_next) {
#pragma unroll
            for (int i = 0; i < 4; ++i)
                pa[i] = apred[i] ? __ldg((const float4*)(A + (size_t)(m0 + arow[i]) * K + knext + ac4[i] * 4))
                                 : make_float4(0.f, 0.f, 0.f, 0.f);
#pragma unroll
            for (int i = 0; i < 2; ++i)
                pb[i] = bpred[i] ? __ldg((const float4*)(B + (size_t)(p0 + brow[i]) * K + knext + bc4[i] * 4))
                                 : make_float4(0.f, 0.f, 0.f, 0.f);
        }

        // ---- MMA on current stage
        const uint32_t* cAH = AH + cur * BMg * ASP;
        const uint32_t* cAL = AL + cur * BMg * ASP;
        const uint32_t* cBH = BH + cur * BNg * BSP;
        const uint32_t* cBL = BL + cur * BNg * BSP;
#pragma unroll
        for (int ks = 0; ks < 2; ++ks) {
            uint32_t ah[2][4], al[2][4], bh[2][4], bl[2][4];
            int akp = ks * 8 + a_kp0;
            int bkp = ks * 8 + b_kp0;
#pragma unroll
            for (int mt = 0; mt < 2; ++mt) {
                int r = wm + mt * 16 + a_row;
                ldsm4(ah[mt], &cAH[r * ASP + akp]);
                ldsm4(al[mt], &cAL[r * ASP + akp]);
            }
#pragma unroll
            for (int p = 0; p < 2; ++p) {
                int n = wn + p * 16 + b_row;
                ldsm4(bh[p], &cBH[n * BSP + bkp]);
                ldsm4(bl[p], &cBL[n * BSP + bkp]);
            }
#pragma unroll
            for (int p = 0; p < 2; ++p) {
#pragma unroll
                for (int half = 0; half < 2; ++half) {
                    int nt = p * 2 + half;
                    uint32_t b0  = bh[p][half * 2], b1  = bh[p][half * 2 + 1];
                    uint32_t lb0 = bl[p][half * 2], lb1 = bl[p][half * 2 + 1];
#pragma unroll
                    for (int mt = 0; mt < 2; ++mt) {
                        mma16816(acc[mt][nt], ah[mt], b0, b1);
                        mma16816(acc[mt][nt], al[mt], b0, b1);
                        mma16816(acc[mt][nt], ah[mt], lb0, lb1);
                    }
                }
            }
        }

        // ---- convert + store prefetched tile into the other stage
        if (has_next) {
            uint32_t* nAH = AH + (cur ^ 1) * BMg * ASP;
            uint32_t* nAL = AL + (cur ^ 1) * BMg * ASP;
            uint32_t* nBH = BH + (cur ^ 1) * BNg * BSP;
            uint32_t* nBL = BL + (cur ^ 1) * BNg * BSP;
#pragma unroll
            for (int i = 0; i < 4; ++i) {
                float4 v = pa[i];
                if (PRELU_A) {
                    v.x = v.x > 0.f ? v.x : alpha * v.x;
                    v.y = v.y > 0.f ? v.y : alpha * v.y;
                    v.z = v.z > 0.f ? v.z : alpha * v.z;
                    v.w = v.w > 0.f ? v.w : alpha * v.w;
                }
                uint32_t h0, h1, l0, l1; cvt4(v, h0, h1, l0, l1);
                int base = arow[i] * ASP + ac4[i] * 2;
                nAH[base] = h0; nAH[base + 1] = h1;
                nAL[base] = l0; nAL[base + 1] = l1;
            }
#pragma unroll
            for (int i = 0; i < 2; ++i) {
                uint32_t h0, h1, l0, l1; cvt4(pb[i], h0, h1, l0, l1);
                int base = brow[i] * BSP + bc4[i] * 2;
                nBH[base] = h0; nBH[base + 1] = h1;
                nBL[base] = l0; nBL[base + 1] = l1;
            }
        }
        __syncthreads();
    }

    // ---- Epilogue
#pragma unroll
    for (int mt = 0; mt < 2; ++mt) {
#pragma unroll
        for (int nt = 0; nt < 4; ++nt) {
            int row0 = m0 + wm + mt * 16 + g;
            int col  = p0 + wn + nt * 8 + tg * 2;
            float b0 = 0.f, b1 = 0.f;
            if (HAS_BIAS) {
                if (col < P)     b0 = __ldg(bias + col);
                if (col + 1 < P) b1 = __ldg(bias + col + 1);
            }
            float ec0 = 0.f, ec1 = 0.f;
            if (FUSED_MS) {
                ec0 = __ldg(emb1 + 4 * D_IN + col) + __ldg(emb2 + col);
                ec1 = __ldg(emb1 + 4 * D_IN + col + 1) + __ldg(emb2 + col + 1);
            }
#pragma unroll
            for (int h = 0; h < 2; ++h) {
                int row = row0 + h * 8;
                if (row >= M) continue;
                float v0 = acc[mt][nt][h * 2 + 0] + b0;
                float v1 = acc[mt][nt][h * 2 + 1] + b1;
                if (RELU_OUT) { v0 = fmaxf(v0, 0.f); v1 = fmaxf(v1, 0.f); }
                if (FUSED_MS) {
                    bool masked = (__ldg(&g_maskbits[row >> 5]) >> (row & 31)) & 1u;
                    if (masked) { v0 = 0.f; v1 = 0.f; }
                    C[(size_t)row * P + col]      = v0;
                    C[(size_t)row * P + col + 1]  = v1;
                    C2[(size_t)row * P + col]     = v0 + ec0;
                    C2[(size_t)row * P + col + 1] = v1 + ec1;
                } else {
                    if (col < P)     C[(size_t)row * P + col]     = v0;
                    if (col + 1 < P) C[(size_t)row * P + col + 1] = v1;
                }
            }
        }
    }
}

// ---------------------------------------------------------------------------
// Build mask bitmap. Single block: zero then set.
// ---------------------------------------------------------------------------
__global__ void maskbits_kernel(const int* __restrict__ mi, int NM)
{
    const int W = (N_NODES + 31) / 32;
    for (int i = threadIdx.x; i < W; i += blockDim.x) g_maskbits[i] = 0u;
    __syncthreads();
    for (int i = threadIdx.x; i < NM; i += blockDim.x) {
        int r = __ldg(mi + i);
        if (r >= 0 && r < N_NODES)
            atomicOr(&g_maskbits[r >> 5], 1u << (r & 31));
    }
}

// ---------------------------------------------------------------------------
// Edge scatter: aggr[dst] += h[src] + emb1[et] + emb2[ed].
// One warp per FOUR edges, software-pipelined gathers, vector red.add.
// ---------------------------------------------------------------------------
__global__ void edge_kernel(const int* __restrict__ ei,
                            const int* __restrict__ ea,
                            const float* __restrict__ emb1,
                            const float* __restrict__ emb2, int E)
{
    int w = (blockIdx.x * blockDim.x + threadIdx.x) >> 5;
    int lane = threadIdx.x & 31;
    int c = lane * 4;
    int base = w * 4;
    if (base >= E) return;

    int src[4], dst[4], et[4], ed[4];
#pragma unroll
    for (int j = 0; j < 4; ++j) {
        int e = base + j;
        if (e < E) {
            src[j] = __ldg(ei + e);
            dst[j] = __ldg(ei + E + e);
            et[j]  = __ldg(ea + 2 * e);
            ed[j]  = __ldg(ea + 2 * e + 1);
        } else { src[j] = 0; dst[j] = -1; et[j] = 0; ed[j] = 0; }
    }
    float4 hv[4], e1[4], e2[4];
#pragma unroll
    for (int j = 0; j < 4; ++j) {
        hv[j] = *(const float4*)(g_h + (size_t)src[j] * D_IN + c);
        e1[j] = __ldg((const float4*)(emb1 + (size_t)et[j] * D_IN + c));
        e2[j] = __ldg((const float4*)(emb2 + (size_t)ed[j] * D_IN + c));
    }
#pragma unroll
    for (int j = 0; j < 4; ++j) {
        if (dst[j] < 0) continue;
        float m0 = hv[j].x + e1[j].x + e2[j].x;
        float m1 = hv[j].y + e1[j].y + e2[j].y;
        float m2 = hv[j].z + e1[j].z + e2[j].z;
        float m3 = hv[j].w + e1[j].w + e2[j].w;
        float* p = g_aggr + (size_t)dst[j] * D_IN + c;
        asm volatile("red.global.add.v4.f32 [%0], {%1, %2, %3, %4};"
                     :: "l"(p), "f"(m0), "f"(m1), "f"(m2), "f"(m3)
                     : "memory");
    }
}

// ---------------------------------------------------------------------------
extern "C" void kernel_launch(void* const* d_in, const int* in_sizes, int n_in,
                              void* d_out, int out_size)
{
    const float* x       = (const float*)d_in[0];
    const int*   ei      = (const int*)d_in[1];
    const int*   ea      = (const int*)d_in[2];
    const int*   mi      = (const int*)d_in[3];
    const float* prelu_a = (const float*)d_in[4];
    const float* W_enc   = (const float*)d_in[5];
    const float* emb1    = (const float*)d_in[6];
    const float* emb2    = (const float*)d_in[7];
    const float* W1      = (const float*)d_in[8];
    const float* b1      = (const float*)d_in[9];
    const float* W2      = (const float*)d_in[10];
    const float* b2      = (const float*)d_in[11];
    float*       out     = (float*)d_out;

    const int N  = in_sizes[0] / D_IN;
    const int E  = in_sizes[1] / 2;
    const int NM = in_sizes[3];

    const int SMEM_BYTES = SMEM_WORDS * 4;   // 61440

    // Idempotent, called every invocation (no static guards -- harness rule)
    cudaFuncSetAttribute(gemm_mma_kernel<true, false, false, true>,
                         cudaFuncAttributeMaxDynamicSharedMemorySize, SMEM_BYTES);
    cudaFuncSetAttribute(gemm_mma_kernel<false, true, true, false>,
                         cudaFuncAttributeMaxDynamicSharedMemorySize, SMEM_BYTES);
    cudaFuncSetAttribute(gemm_mma_kernel<false, false, true, false>,
                         cudaFuncAttributeMaxDynamicSharedMemorySize, SMEM_BYTES);

    float *h_ptr, *aggr_ptr, *hid_ptr;
    cudaGetSymbolAddress((void**)&h_ptr, g_h);
    cudaGetSymbolAddress((void**)&aggr_ptr, g_aggr);
    cudaGetSymbolAddress((void**)&hid_ptr, g_hid);

    // 0) mask bitmap
    maskbits_kernel<<<1, 1024>>>(mi, NM);

    // 1) h = mask(prelu(x) @ W_enc^T); aggr = h + emb1[4]+emb2[0]   (fused)
    {
        dim3 grid((D_IN + 63) / 64, (N + 127) / 128);
        gemm_mma_kernel<true, false, false, true><<<grid, 256, SMEM_BYTES>>>(
            x, W_enc, nullptr, h_ptr, aggr_ptr, N, D_IN, D_IN, prelu_a, emb1, emb2);
    }
    // 2) edge scatter-add (4 edges per warp)
    {
        int warps = (E + 3) / 4;
        long long threads = (long long)warps * 32;
        edge_kernel<<<(int)((threads + 255) / 256), 256>>>(ei, ea, emb1, emb2, E);
    }
    // 3) hid = relu(aggr @ W1^T + b1)
    {
        dim3 grid((D_FF + 63) / 64, (N + 127) / 128);
        gemm_mma_kernel<false, true, true, false><<<grid, 256, SMEM_BYTES>>>(
            aggr_ptr, W1, b1, hid_ptr, nullptr, N, D_IN, D_FF, nullptr, nullptr, nullptr);
    }
    // 4) out = hid @ W2^T + b2
    {
        dim3 grid((D_OUT + 63) / 64, (N + 127) / 128);
        gemm_mma_kernel<false, false, true, false><<<grid, 256, SMEM_BYTES>>>(
            hid_ptr, W2, b2, out, nullptr, N, D_FF, D_OUT, nullptr, nullptr, nullptr);
    }
}